// round 16
// baseline (speedup 1.0000x reference)
#include <cuda_runtime.h>
#include <cstdint>
#include <cstddef>

#define NROWS 65536
#define DIMD  128
#define KC    1024
#define CT    64
#define NTILES (KC / CT)
#define RPB   64
#define SMEMSZ (128*64*4 + 128*64*4 + 64*4 + 64*4)

typedef unsigned long long u64;

// Device-global scratch (allocation-free per harness rules)
__device__ u64 g_S[KC * DIMD];   // fixed-point scatter sums (x * 2^40)
__device__ u64 g_loss;           // fixed-point sum of sq diffs (* 2^30)
__device__ float g_csq[KC];

// threefry2x32, key = jax.random.key(42) = [0, 42]; partitionable 32-bit draws:
// counter (hi=0, lo=j), bits = out0 ^ out1.  (Verified exact since R5.)
__device__ __forceinline__ uint32_t tf_xor(uint32_t c1) {
    const uint32_t ks0 = 0u, ks1 = 42u, ks2 = 0x1BD11BF0u;
    uint32_t x0 = 0u, x1 = c1 + ks1;
#define TFR(r) { x0 += x1; x1 = __funnelshift_l(x1, x1, (r)); x1 ^= x0; }
    TFR(13) TFR(15) TFR(26) TFR(6)   x0 += ks1; x1 += ks2 + 1u;
    TFR(17) TFR(29) TFR(16) TFR(24)  x0 += ks2; x1 += ks0 + 2u;
    TFR(13) TFR(15) TFR(26) TFR(6)   x0 += ks0; x1 += ks1 + 3u;
    TFR(17) TFR(29) TFR(16) TFR(24)  x0 += ks1; x1 += ks2 + 4u;
    TFR(13) TFR(15) TFR(26) TFR(6)   x0 += ks2; x1 += ks0 + 5u;
#undef TFR
    return x0 ^ x1;
}

// JAX gumbel: u = max(tiny, fl(bits_float - 1) + tiny); g = -log(-log(u))
__device__ __forceinline__ float gumbel_of(uint32_t bits) {
    const float tiny = 1.17549435e-38f;
    float f = __fsub_rn(__uint_as_float((bits >> 9) | 0x3F800000u), 1.0f);
    float u = fmaxf(tiny, __fadd_rn(f, tiny));
    return -logf(-logf(u));
}

// Packed dual ops (each lane IEEE fp32 rn — bit-identical to scalar sequence)
__device__ __forceinline__ void ffma2(u64& d, u64 a, u64 b) {
    asm("fma.rn.f32x2 %0, %1, %2, %0;" : "+l"(d) : "l"(a), "l"(b));
}
__device__ __forceinline__ u64 dup2(float v) {
    u64 r; asm("mov.b64 %0, {%1, %1};" : "=l"(r) : "f"(v)); return r;
}
__device__ __forceinline__ u64 add2(u64 a, u64 b) {
    u64 r; asm("add.rn.f32x2 %0, %1, %2;" : "=l"(r) : "l"(a), "l"(b)); return r;
}
__device__ __forceinline__ u64 mul2(u64 a, u64 b) {
    u64 r; asm("mul.rn.f32x2 %0, %1, %2;" : "=l"(r) : "l"(a), "l"(b)); return r;
}
__device__ __forceinline__ u64 sub2(u64 a, u64 b) {
    u64 r; asm("sub.rn.f32x2 %0, %1, %2;" : "=l"(r) : "l"(a), "l"(b)); return r;
}
__device__ __forceinline__ void unpack2(u64 v, float& lo, float& hi) {
    asm("mov.b64 {%0, %1}, %2;" : "=f"(lo), "=f"(hi) : "l"(v));
}

// ---- prep: zero accumulators + fp64-exact codebook sq-norms rounded to f32 ----
__global__ void k_prep(const float* __restrict__ cb) {
    int k = blockIdx.x, t = threadIdx.x;
    g_S[k * DIMD + t] = 0ull;
    if (k == 0 && t == 0) g_loss = 0ull;
    float v = cb[k * DIMD + t];
    __shared__ double red[128];
    red[t] = (double)v * (double)v;
    __syncthreads();
    for (int o = 64; o > 0; o >>= 1) { if (t < o) red[t] += red[t + o]; __syncthreads(); }
    if (t == 0) g_csq[k] = (float)red[0];
}

// ---- main: occ-3 (24 warps/SM) distances + filtered gumbel + fused tail ----
// 64 rows/block, CT=64 codes per tile (16 tiles); warp w owns rows [8w, 8w+8);
// thread covers 8 rows x 2 codes (codes 2l, 2l+1 of each tile).
__global__ void __launch_bounds__(256, 3) k_main(const float* __restrict__ x,
                                                 const float* __restrict__ cb,
                                                 float* __restrict__ codes) {
    extern __shared__ float sm[];
    float* xs  = sm;                   // [128][64]  x tile transposed [d][localrow]
    float* cs  = sm + 128 * 64;        // [128][64]  codebook tile transposed [d][code]
    float* asq = cs + 128 * 64;        // [64]
    float* bsq = asq + 64;             // [64]

    const int tid = threadIdx.x;
    const int w = tid >> 5, l = tid & 31;
    const int r0 = blockIdx.x * RPB;
    const u64 two2 = dup2(2.0f);
    const uint32_t ctr0 = (uint32_t)(r0 + 8 * w) * 1024u;

    // Load x tile transposed: row j = tid>>2 (0..63), quarter q = tid&3
    {
        int j = tid >> 2, q = tid & 3;
        const float4* src = (const float4*)(x + (size_t)(r0 + j) * DIMD);
#pragma unroll
        for (int i = 0; i < 8; i++) {
            int f4 = q * 8 + i;
            float4 v = src[f4];
            int d = f4 * 4;
            xs[(d + 0) * 64 + j] = v.x; xs[(d + 1) * 64 + j] = v.y;
            xs[(d + 2) * 64 + j] = v.z; xs[(d + 3) * 64 + j] = v.w;
        }
    }
    __syncthreads();

    // Row sq-norms in fp64, rounded once to f32
    if (tid < 64) {
        double s0 = 0, s1 = 0, s2 = 0, s3 = 0;
#pragma unroll
        for (int d = 0; d < 128; d += 4) {
            double a = (double)xs[(d + 0) * 64 + tid]; s0 += a * a;
            double b = (double)xs[(d + 1) * 64 + tid]; s1 += b * b;
            double c = (double)xs[(d + 2) * 64 + tid]; s2 += c * c;
            double e = (double)xs[(d + 3) * 64 + tid]; s3 += e * e;
        }
        asq[tid] = (float)((s0 + s1) + (s2 + s3));
    }
    __syncthreads();

    u64 aap[4];
#pragma unroll
    for (int p = 0; p < 4; p++)
        aap[p] = *(const u64*)(asq + 8 * w + 2 * p);

    float bestv[8], fbest[8];
    int   besti[8];
#pragma unroll
    for (int r = 0; r < 8; r++) { bestv[r] = -1e30f; fbest[r] = -1e30f; besti[r] = 0; }

    for (int tt = 0; tt < NTILES; tt++) {
        const int cbase = tt * CT;
        __syncthreads();
        {   // load codebook tile transposed: code c = tid>>2 (0..63), quarter h
            int c = tid >> 2, h = tid & 3;
            const float4* src = (const float4*)(cb + (size_t)(cbase + c) * DIMD + h * 32);
#pragma unroll
            for (int i = 0; i < 8; i++) {
                float4 v = src[i];
                int d = h * 32 + i * 4;
                cs[(d + 0) * 64 + c] = v.x; cs[(d + 1) * 64 + c] = v.y;
                cs[(d + 2) * 64 + c] = v.z; cs[(d + 3) * 64 + c] = v.w;
            }
            if (tid < 64) bsq[tid] = g_csq[cbase + tid];
        }
        __syncthreads();

        // accq[p][c]: packed accumulator for row pair (8w+2p, 8w+2p+1), code 2l+c
        u64 accq[4][2];
#pragma unroll
        for (int p = 0; p < 4; p++) { accq[p][0] = 0ull; accq[p][1] = 0ull; }

#pragma unroll 8
        for (int k = 0; k < 128; k++) {
            const u64* xp = (const u64*)(xs + k * 64 + 8 * w);
            u64 a0 = xp[0], a1 = xp[1], a2 = xp[2], a3 = xp[3];
            float2 cv = *(const float2*)&cs[k * 64 + 2 * l];
            u64 bx = dup2(cv.x), by = dup2(cv.y);
            ffma2(accq[0][0], a0, bx); ffma2(accq[0][1], a0, by);
            ffma2(accq[1][0], a1, bx); ffma2(accq[1][1], a1, by);
            ffma2(accq[2][0], a2, bx); ffma2(accq[2][1], a2, by);
            ffma2(accq[3][0], a3, bx); ffma2(accq[3][1], a3, by);
        }

#pragma unroll
        for (int cc = 0; cc < 2; cc++) {
            const int code = cbase + 2 * l + cc;
            const u64 bb = dup2(bsq[2 * l + cc]);
#pragma unroll
            for (int p = 0; p < 4; p++) {
                // d2 = fl(fl(a+b) - fl(2*dot)) per lane — exact reference sequence
                u64 d2q = sub2(add2(aap[p], bb), mul2(two2, accq[p][cc]));
                float d2v[2];
                unpack2(d2q, d2v[0], d2v[1]);
#pragma unroll
                for (int h2 = 0; h2 < 2; h2++) {
                    const int r = 2 * p + h2;
                    const uint32_t bits =
                        tf_xor(ctr0 + (uint32_t)r * 1024u + (uint32_t)code);
                    const float d2c = fmaxf(d2v[h2], 1e-12f);
                    // Sound upper bound: g <= (clz(2^23 - (bits>>9)) - 8)*ln2 (+pad)
                    const int kk = 0x800000 - (int)(bits >> 9);
                    const float gub =
                        fmaf(__int2float_rn(__clz(kk)), 0.69314724f, -5.5451576f);
                    const float uu = gub - fbest[r];
                    const bool take = (uu > 0.0f) && (d2c < uu * uu * 1.0000002f);
                    if (__any_sync(0xffffffffu, take)) {
                        float z = __fsub_rn(gumbel_of(bits), sqrtf(d2c));
                        if (z > bestv[r]) { bestv[r] = z; besti[r] = code; }
                    }
                }
            }
        }

        // Refresh warp-wide filter threshold (fbest >= every lane's bestv)
#pragma unroll
        for (int r = 0; r < 8; r++) {
            float m = bestv[r];
#pragma unroll
            for (int o = 16; o > 0; o >>= 1)
                m = fmaxf(m, __shfl_xor_sync(0xffffffffu, m, o));
            fbest[r] = m;
        }
    }

    // Tail per row: warp argmax (ties -> lowest index), one-hot write, scatter, loss
    u64 qacc = 0ull;
#pragma unroll
    for (int r = 0; r < 8; r++) {
        float v = bestv[r];
        int   i = besti[r];
#pragma unroll
        for (int o = 16; o > 0; o >>= 1) {
            float v2 = __shfl_xor_sync(0xffffffffu, v, o);
            int   i2 = __shfl_xor_sync(0xffffffffu, i, o);
            if (v2 > v || (v2 == v && i2 < i)) { v = v2; i = i2; }
        }
        const int row = r0 + 8 * w + r;

        // one-hot row: 8 x float4 per lane
        float4* dst = (float4*)(codes + (size_t)row * KC + 32 * l);
        const int rel = i - 32 * l;
#pragma unroll
        for (int q2 = 0; q2 < 8; q2++) {
            float4 v4 = make_float4(0.f, 0.f, 0.f, 0.f);
            int d = rel - 4 * q2;
            if (d == 0) v4.x = 1.0f; else if (d == 1) v4.y = 1.0f;
            else if (d == 2) v4.z = 1.0f; else if (d == 3) v4.w = 1.0f;
            dst[q2] = v4;
        }

        // scatter + loss partials (fp32 fixed-point, order-free atomics)
        float4 xv = *(const float4*)(x + (size_t)row * DIMD + 4 * l);
        float4 cv = *(const float4*)(cb + (size_t)i * DIMD + 4 * l);
        u64* sd = &g_S[(size_t)i * DIMD + 4 * l];
        atomicAdd(sd + 0, (u64)__float2ll_rn(xv.x * 1.099511627776e12f));
        atomicAdd(sd + 1, (u64)__float2ll_rn(xv.y * 1.099511627776e12f));
        atomicAdd(sd + 2, (u64)__float2ll_rn(xv.z * 1.099511627776e12f));
        atomicAdd(sd + 3, (u64)__float2ll_rn(xv.w * 1.099511627776e12f));
        float dx = cv.x - xv.x, dy = cv.y - xv.y, dz = cv.z - xv.z, dw = cv.w - xv.w;
        qacc += (u64)(__float2ll_rn(dx * dx * 1073741824.0f)
                    + __float2ll_rn(dy * dy * 1073741824.0f)
                    + __float2ll_rn(dz * dz * 1073741824.0f)
                    + __float2ll_rn(dw * dw * 1073741824.0f));
    }
    // one loss atomic per warp
#pragma unroll
    for (int o = 16; o > 0; o >>= 1)
        qacc += __shfl_xor_sync(0xffffffffu, qacc, o);
    if (l == 0) atomicAdd(&g_loss, qacc);
}

// ---- finalize: loss scalar + EMA codebook ----
__global__ void k_final(const float* __restrict__ cb, float* __restrict__ out, size_t osz) {
    const size_t base = (size_t)NROWS * KC;
    if (osz < base + 1 + (size_t)KC * DIMD) return;
    int k = blockIdx.x, d = threadIdx.x;
    if (k < KC) {
        long long s = (long long)g_S[k * DIMD + d];
        float sum = (float)((double)s * (1.0 / 1099511627776.0));
        out[base + 1 + (size_t)k * DIMD + d] = 0.99f * cb[k * DIMD + d]
                                             + (float)(1.0 - 0.99) * sum;
    } else if (d == 0) {
        double sq = (double)(long long)g_loss * (1.0 / 1073741824.0);
        out[base] = (float)(1.25 * sq / 8388608.0);
    }
}

extern "C" void kernel_launch(void* const* d_in, const int* in_sizes, int n_in,
                              void* d_out, int out_size) {
    const float* x  = (const float*)d_in[0];
    const float* cb = (const float*)d_in[1];
    float* out = (float*)d_out;

    cudaFuncSetAttribute(k_main, cudaFuncAttributeMaxDynamicSharedMemorySize, SMEMSZ);

    k_prep<<<KC, 128>>>(cb);
    k_main<<<NROWS / RPB, 256, SMEMSZ>>>(x, cb, out);
    k_final<<<KC + 1, 128>>>(cb, out, (size_t)out_size);
}

// round 17
// speedup vs baseline: 1.1994x; 1.1994x over previous
#include <cuda_runtime.h>
#include <cstdint>
#include <cstddef>

#define NROWS 65536
#define DIMD  128
#define KC    1024
#define CT    128
#define NTILES (KC / CT)
#define RPB   64
#define SMEMSZ (128*64*4 + 128*128*4 + 64*4 + 128*4)

typedef unsigned long long u64;

// Device-global scratch (allocation-free per harness rules)
__device__ u64 g_S[KC * DIMD];   // fixed-point scatter sums (x * 2^40)
__device__ u64 g_loss;           // fixed-point sum of sq diffs (* 2^30)
__device__ float g_csq[KC];

// threefry2x32, key = jax.random.key(42) = [0, 42]; partitionable 32-bit draws:
// counter (hi=0, lo=j), bits = out0 ^ out1.  (Verified exact since R5.)
__device__ __forceinline__ uint32_t tf_xor(uint32_t c1) {
    const uint32_t ks0 = 0u, ks1 = 42u, ks2 = 0x1BD11BF0u;
    uint32_t x0 = 0u, x1 = c1 + ks1;
#define TFR(r) { x0 += x1; x1 = __funnelshift_l(x1, x1, (r)); x1 ^= x0; }
    TFR(13) TFR(15) TFR(26) TFR(6)   x0 += ks1; x1 += ks2 + 1u;
    TFR(17) TFR(29) TFR(16) TFR(24)  x0 += ks2; x1 += ks0 + 2u;
    TFR(13) TFR(15) TFR(26) TFR(6)   x0 += ks0; x1 += ks1 + 3u;
    TFR(17) TFR(29) TFR(16) TFR(24)  x0 += ks1; x1 += ks2 + 4u;
    TFR(13) TFR(15) TFR(26) TFR(6)   x0 += ks2; x1 += ks0 + 5u;
#undef TFR
    return x0 ^ x1;
}

// JAX gumbel: u = max(tiny, fl(bits_float - 1) + tiny); g = -log(-log(u))
__device__ __forceinline__ float gumbel_of(uint32_t bits) {
    const float tiny = 1.17549435e-38f;
    float f = __fsub_rn(__uint_as_float((bits >> 9) | 0x3F800000u), 1.0f);
    float u = fmaxf(tiny, __fadd_rn(f, tiny));
    return -logf(-logf(u));
}

// Packed dual ops (each lane IEEE fp32 rn — bit-identical to scalar sequence)
__device__ __forceinline__ void ffma2(u64& d, u64 a, u64 b) {
    asm("fma.rn.f32x2 %0, %1, %2, %0;" : "+l"(d) : "l"(a), "l"(b));
}
__device__ __forceinline__ u64 dup2(float v) {
    u64 r; asm("mov.b64 %0, {%1, %1};" : "=l"(r) : "f"(v)); return r;
}
__device__ __forceinline__ u64 add2(u64 a, u64 b) {
    u64 r; asm("add.rn.f32x2 %0, %1, %2;" : "=l"(r) : "l"(a), "l"(b)); return r;
}
__device__ __forceinline__ u64 mul2(u64 a, u64 b) {
    u64 r; asm("mul.rn.f32x2 %0, %1, %2;" : "=l"(r) : "l"(a), "l"(b)); return r;
}
__device__ __forceinline__ u64 sub2(u64 a, u64 b) {
    u64 r; asm("sub.rn.f32x2 %0, %1, %2;" : "=l"(r) : "l"(a), "l"(b)); return r;
}
__device__ __forceinline__ void unpack2(u64 v, float& lo, float& hi) {
    asm("mov.b64 {%0, %1}, %2;" : "=f"(lo), "=f"(hi) : "l"(v));
}

// ---- prep: zero accumulators + fp64-exact codebook sq-norms rounded to f32 ----
__global__ void k_prep(const float* __restrict__ cb) {
    int k = blockIdx.x, t = threadIdx.x;
    g_S[k * DIMD + t] = 0ull;
    if (k == 0 && t == 0) g_loss = 0ull;
    float v = cb[k * DIMD + t];
    __shared__ double red[128];
    red[t] = (double)v * (double)v;
    __syncthreads();
    for (int o = 64; o > 0; o >>= 1) { if (t < o) red[t] += red[t + o]; __syncthreads(); }
    if (t == 0) g_csq[k] = (float)red[0];
}

// ---- main: distances + filtered gumbel + argmax + fused one-hot/scatter/loss ----
// 64 rows/block; warp w owns rows [8w, 8w+8); thread covers 8 rows x 4 codes.
__global__ void __launch_bounds__(256, 2) k_main(const float* __restrict__ x,
                                                 const float* __restrict__ cb,
                                                 float* __restrict__ codes) {
    extern __shared__ float sm[];
    float* xs  = sm;                   // [128][64]  x tile transposed [d][localrow]
    float* cs  = sm + 128 * 64;        // [128][128] codebook tile transposed [d][code]
    float* asq = cs + 128 * 128;       // [64]
    float* bsq = asq + 64;             // [128]

    const int tid = threadIdx.x;
    const int w = tid >> 5, l = tid & 31;
    const int r0 = blockIdx.x * RPB;
    const u64 two2 = dup2(2.0f);

    // Load x tile transposed: row j = tid>>2 (0..63), quarter q = tid&3
    {
        int j = tid >> 2, q = tid & 3;
        const float4* src = (const float4*)(x + (size_t)(r0 + j) * DIMD);
#pragma unroll
        for (int i = 0; i < 8; i++) {
            int f4 = q * 8 + i;
            float4 v = src[f4];
            int d = f4 * 4;
            xs[(d + 0) * 64 + j] = v.x; xs[(d + 1) * 64 + j] = v.y;
            xs[(d + 2) * 64 + j] = v.z; xs[(d + 3) * 64 + j] = v.w;
        }
    }
    __syncthreads();

    // Row sq-norms in fp64, rounded once to f32
    if (tid < 64) {
        double s0 = 0, s1 = 0, s2 = 0, s3 = 0;
#pragma unroll
        for (int d = 0; d < 128; d += 4) {
            double a = (double)xs[(d + 0) * 64 + tid]; s0 += a * a;
            double b = (double)xs[(d + 1) * 64 + tid]; s1 += b * b;
            double c = (double)xs[(d + 2) * 64 + tid]; s2 += c * c;
            double e = (double)xs[(d + 3) * 64 + tid]; s3 += e * e;
        }
        asq[tid] = (float)((s0 + s1) + (s2 + s3));
    }

    float bestv[8], fbest[8];
    int   besti[8];
#pragma unroll
    for (int r = 0; r < 8; r++) { bestv[r] = -1e30f; fbest[r] = -1e30f; besti[r] = 0; }

    for (int tt = 0; tt < NTILES; tt++) {
        const int cbase = tt * CT;
        __syncthreads();
        {   // load codebook tile transposed
            int c = tid >> 1, h = tid & 1;
            const float4* src = (const float4*)(cb + (size_t)(cbase + c) * DIMD + h * 64);
#pragma unroll
            for (int i = 0; i < 16; i++) {
                float4 v = src[i];
                int d = h * 64 + i * 4;
                cs[(d + 0) * 128 + c] = v.x; cs[(d + 1) * 128 + c] = v.y;
                cs[(d + 2) * 128 + c] = v.z; cs[(d + 3) * 128 + c] = v.w;
            }
            if (tid < 128) bsq[tid] = g_csq[cbase + tid];
        }
        __syncthreads();

        // accq[p][c]: packed accumulator for row pair (8w+2p, 8w+2p+1), code 4l+c
        u64 accq[4][4];
#pragma unroll
        for (int p = 0; p < 4; p++)
#pragma unroll
            for (int cc = 0; cc < 4; cc++) accq[p][cc] = 0ull;

#pragma unroll 8
        for (int k = 0; k < 128; k++) {
            const u64* xp = (const u64*)(xs + k * 64 + 8 * w);
            u64 a0 = xp[0], a1 = xp[1], a2 = xp[2], a3 = xp[3];
            float4 cv = *(const float4*)&cs[k * 128 + 4 * l];
            u64 bx = dup2(cv.x), by = dup2(cv.y), bz = dup2(cv.z), bw = dup2(cv.w);
            ffma2(accq[0][0], a0, bx); ffma2(accq[0][1], a0, by);
            ffma2(accq[0][2], a0, bz); ffma2(accq[0][3], a0, bw);
            ffma2(accq[1][0], a1, bx); ffma2(accq[1][1], a1, by);
            ffma2(accq[1][2], a1, bz); ffma2(accq[1][3], a1, bw);
            ffma2(accq[2][0], a2, bx); ffma2(accq[2][1], a2, by);
            ffma2(accq[2][2], a2, bz); ffma2(accq[2][3], a2, bw);
            ffma2(accq[3][0], a3, bx); ffma2(accq[3][1], a3, by);
            ffma2(accq[3][2], a3, bz); ffma2(accq[3][3], a3, bw);
        }

        u64 aap[4];
#pragma unroll
        for (int p = 0; p < 4; p++)
            aap[p] = *(const u64*)(asq + 8 * w + 2 * p);
        const uint32_t ctr0 = (uint32_t)(r0 + 8 * w) * 1024u;

#pragma unroll
        for (int cc = 0; cc < 4; cc++) {
            const int code = cbase + 4 * l + cc;
            const u64 bb = dup2(bsq[4 * l + cc]);
#pragma unroll
            for (int p = 0; p < 4; p++) {
                // d2 = fl(fl(a+b) - fl(2*dot)) per lane — exact reference sequence
                u64 d2q = sub2(add2(aap[p], bb), mul2(two2, accq[p][cc]));
                float d2lo, d2hi;
                unpack2(d2q, d2lo, d2hi);
                const int rA = 2 * p, rB = 2 * p + 1;
                const uint32_t bitsA =
                    tf_xor(ctr0 + (uint32_t)rA * 1024u + (uint32_t)code);
                const uint32_t bitsB =
                    tf_xor(ctr0 + (uint32_t)rB * 1024u + (uint32_t)code);
                const float d2cA = fmaxf(d2lo, 1e-12f);
                const float d2cB = fmaxf(d2hi, 1e-12f);
                // Sound upper bound: g <= (clz(2^23 - (bits>>9)) - 8)*ln2 (+pad)
                const int kkA = 0x800000 - (int)(bitsA >> 9);
                const int kkB = 0x800000 - (int)(bitsB >> 9);
                const float gubA =
                    fmaf(__int2float_rn(__clz(kkA)), 0.69314724f, -5.5451576f);
                const float gubB =
                    fmaf(__int2float_rn(__clz(kkB)), 0.69314724f, -5.5451576f);
                const float uuA = gubA - fbest[rA];
                const float uuB = gubB - fbest[rB];
                const bool takeA = (uuA > 0.0f) && (d2cA < uuA * uuA * 1.0000002f);
                const bool takeB = (uuB > 0.0f) && (d2cB < uuB * uuB * 1.0000002f);
                // one vote per packed pair; on pass, compute TRUE z for both and
                // update via z>bestv (exact — filter only ever conservative)
                if (__any_sync(0xffffffffu, takeA || takeB)) {
                    float zA = __fsub_rn(gumbel_of(bitsA), sqrtf(d2cA));
                    float zB = __fsub_rn(gumbel_of(bitsB), sqrtf(d2cB));
                    if (zA > bestv[rA]) { bestv[rA] = zA; besti[rA] = code; }
                    if (zB > bestv[rB]) { bestv[rB] = zB; besti[rB] = code; }
                }
            }
        }

        // Refresh warp-wide filter threshold (fbest >= every lane's bestv)
#pragma unroll
        for (int r = 0; r < 8; r++) {
            float m = bestv[r];
#pragma unroll
            for (int o = 16; o > 0; o >>= 1)
                m = fmaxf(m, __shfl_xor_sync(0xffffffffu, m, o));
            fbest[r] = m;
        }
    }

    // Tail per row: warp argmax (ties -> lowest index), one-hot write, scatter, loss
    u64 qacc = 0ull;
#pragma unroll
    for (int r = 0; r < 8; r++) {
        float v = bestv[r];
        int   i = besti[r];
#pragma unroll
        for (int o = 16; o > 0; o >>= 1) {
            float v2 = __shfl_xor_sync(0xffffffffu, v, o);
            int   i2 = __shfl_xor_sync(0xffffffffu, i, o);
            if (v2 > v || (v2 == v && i2 < i)) { v = v2; i = i2; }
        }
        const int row = r0 + 8 * w + r;

        // one-hot row: 8 x float4 per lane
        float4* dst = (float4*)(codes + (size_t)row * KC + 32 * l);
        const int rel = i - 32 * l;
#pragma unroll
        for (int q2 = 0; q2 < 8; q2++) {
            float4 v4 = make_float4(0.f, 0.f, 0.f, 0.f);
            int d = rel - 4 * q2;
            if (d == 0) v4.x = 1.0f; else if (d == 1) v4.y = 1.0f;
            else if (d == 2) v4.z = 1.0f; else if (d == 3) v4.w = 1.0f;
            dst[q2] = v4;
        }

        // scatter + loss partials (fp32 fixed-point, order-free atomics)
        float4 xv = *(const float4*)(x + (size_t)row * DIMD + 4 * l);
        float4 cv = *(const float4*)(cb + (size_t)i * DIMD + 4 * l);
        u64* sd = &g_S[(size_t)i * DIMD + 4 * l];
        atomicAdd(sd + 0, (u64)__float2ll_rn(xv.x * 1.099511627776e12f));
        atomicAdd(sd + 1, (u64)__float2ll_rn(xv.y * 1.099511627776e12f));
        atomicAdd(sd + 2, (u64)__float2ll_rn(xv.z * 1.099511627776e12f));
        atomicAdd(sd + 3, (u64)__float2ll_rn(xv.w * 1.099511627776e12f));
        float dx = cv.x - xv.x, dy = cv.y - xv.y, dz = cv.z - xv.z, dw = cv.w - xv.w;
        qacc += (u64)(__float2ll_rn(dx * dx * 1073741824.0f)
                    + __float2ll_rn(dy * dy * 1073741824.0f)
                    + __float2ll_rn(dz * dz * 1073741824.0f)
                    + __float2ll_rn(dw * dw * 1073741824.0f));
    }
    // one loss atomic per warp
#pragma unroll
    for (int o = 16; o > 0; o >>= 1)
        qacc += __shfl_xor_sync(0xffffffffu, qacc, o);
    if (l == 0) atomicAdd(&g_loss, qacc);
}

// ---- finalize: loss scalar + EMA codebook ----
__global__ void k_final(const float* __restrict__ cb, float* __restrict__ out, size_t osz) {
    const size_t base = (size_t)NROWS * KC;
    if (osz < base + 1 + (size_t)KC * DIMD) return;
    int k = blockIdx.x, d = threadIdx.x;
    if (k < KC) {
        long long s = (long long)g_S[k * DIMD + d];
        float sum = (float)((double)s * (1.0 / 1099511627776.0));
        out[base + 1 + (size_t)k * DIMD + d] = 0.99f * cb[k * DIMD + d]
                                             + (float)(1.0 - 0.99) * sum;
    } else if (d == 0) {
        double sq = (double)(long long)g_loss * (1.0 / 1073741824.0);
        out[base] = (float)(1.25 * sq / 8388608.0);
    }
}

extern "C" void kernel_launch(void* const* d_in, const int* in_sizes, int n_in,
                              void* d_out, int out_size) {
    const float* x  = (const float*)d_in[0];
    const float* cb = (const float*)d_in[1];
    float* out = (float*)d_out;

    cudaFuncSetAttribute(k_main, cudaFuncAttributeMaxDynamicSharedMemorySize, SMEMSZ);

    k_prep<<<KC, 128>>>(cb);
    k_main<<<NROWS / RPB, 256, SMEMSZ>>>(x, cb, out);
    k_final<<<KC + 1, 128>>>(cb, out, (size_t)out_size);
}